// round 2
// baseline (speedup 1.0000x reference)
#include <cuda_runtime.h>
#include <math.h>

// Problem constants
#define IN_DIM 44
#define H      128
#define H4     512
#define NL     4
#define TDEC   50
#define BATCH  2048
#define SEQ    200

#define TB  16   // batch tile per block (encoder recurrent)
#define DTB 8    // batch tile per block (decoder)

typedef unsigned long long ull;

// ---------------------------------------------------------------------------
// Device scratch (static globals: allocation-free kernel_launch)
// ---------------------------------------------------------------------------
__device__ float g_Xg[(long)SEQ * BATCH * H4];  // precomputed input-gate contributions (+bias)
__device__ float g_ys[(long)SEQ * BATCH * H];   // layer output sequence (reused per layer)
__device__ float g_h[NL * BATCH * H];           // final encoder h per layer
__device__ float g_c[NL * BATCH * H];           // final encoder c per layer
// transposed weights: WT[k][g] layout ([K][4H])
__device__ float g_encWih0T[IN_DIM * H4];
__device__ float g_encWihRT[3 * H * H4];
__device__ float g_encWhhT[NL * H * H4];
__device__ float g_decWih0T[IN_DIM * H4];
__device__ float g_decWihRT[3 * H * H4];
__device__ float g_decWhhT[NL * H * H4];
__device__ float g_fcT[H * IN_DIM];

// ---------------------------------------------------------------------------
// packed f32x2 helpers (FFMA2 — 2x fp32 FMA per instruction on sm_103a)
// ---------------------------------------------------------------------------
__device__ __forceinline__ ull pack2(float a, float b) {
    ull r; asm("mov.b64 %0, {%1,%2};" : "=l"(r) : "f"(a), "f"(b)); return r;
}
__device__ __forceinline__ void unpack2(ull v, float& a, float& b) {
    asm("mov.b64 {%0,%1}, %2;" : "=f"(a), "=f"(b) : "l"(v));
}
__device__ __forceinline__ void ffma2(ull& d, ull a, ull b) {
    asm("fma.rn.f32x2 %0, %1, %2, %0;" : "+l"(d) : "l"(a), "l"(b));
}

__device__ __forceinline__ float sigf(float x) { return 1.0f / (1.0f + expf(-x)); }

// ---------------------------------------------------------------------------
// Generic transpose: src [R][C] -> dst[c*R + r]
// ---------------------------------------------------------------------------
__global__ void k_transpose(const float* __restrict__ src, float* __restrict__ dst,
                            int R, int C) {
    int i = blockIdx.x * blockDim.x + threadIdx.x;
    if (i < R * C) {
        int r = i / C, c = i % C;
        dst[c * R + r] = src[i];
    }
}

// ---------------------------------------------------------------------------
// Input GEMM: out[r][n] = bias[n] + sum_k A(r,k) * WT[k][n]
//   r in [0, SEQ*BATCH), n in [0, 512)
//   GATHER: A(r,k) = x[(b*SEQ + t)*44 + k] with r = t*BATCH + b (encoder layer 0)
//   else:   A(r,k) = A[r*KDIM + k]                         (ys of previous layer)
// Tiled 64x64, BK=16, 256 threads, 4x4 microkernel with FFMA2.
// ---------------------------------------------------------------------------
template <int KDIM, bool GATHER>
__global__ void __launch_bounds__(256) k_ingemm(const float* __restrict__ A,
                                                const float* __restrict__ WT,
                                                const float* __restrict__ bias,
                                                float* __restrict__ out) {
    __shared__ float As[16][65];
    __shared__ float Bs[16][64];
    const int m0 = blockIdx.x * 64;
    const int n0 = blockIdx.y * 64;
    const int tid = threadIdx.x;
    const int tx = tid & 15, ty = tid >> 4;

    ull acc[4][2];
    ull z = pack2(0.f, 0.f);
#pragma unroll
    for (int r = 0; r < 4; ++r) { acc[r][0] = z; acc[r][1] = z; }

    const int KT = (KDIM + 15) / 16;
    for (int kb = 0; kb < KT; ++kb) {
        const int k0 = kb * 16;
#pragma unroll
        for (int i = 0; i < 4; ++i) {
            int idx = tid + i * 256;
            // A tile (store transposed, padded)
            int ka = idx & 15, ma = idx >> 4;
            float va = 0.f;
            if (k0 + ka < KDIM) {
                long off;
                if (GATHER) {
                    int row = m0 + ma;
                    int t = row >> 11;           // BATCH = 2048
                    int b = row & 2047;
                    off = ((long)b * SEQ + t) * KDIM + (k0 + ka);
                } else {
                    off = (long)(m0 + ma) * KDIM + (k0 + ka);
                }
                va = A[off];
            }
            As[ka][ma] = va;
            // B tile
            int nb = idx & 63, kbb = idx >> 6;
            float vb = (k0 + kbb < KDIM) ? WT[(k0 + kbb) * H4 + n0 + nb] : 0.f;
            Bs[kbb][nb] = vb;
        }
        __syncthreads();
#pragma unroll
        for (int k = 0; k < 16; ++k) {
            ull b01 = *(const ull*)&Bs[k][tx * 4];
            ull b23 = *(const ull*)&Bs[k][tx * 4 + 2];
#pragma unroll
            for (int r = 0; r < 4; ++r) {
                float a = As[k][ty * 4 + r];
                ull aa = pack2(a, a);
                ffma2(acc[r][0], aa, b01);
                ffma2(acc[r][1], aa, b23);
            }
        }
        __syncthreads();
    }
    float bi0 = bias[n0 + tx * 4 + 0];
    float bi1 = bias[n0 + tx * 4 + 1];
    float bi2 = bias[n0 + tx * 4 + 2];
    float bi3 = bias[n0 + tx * 4 + 3];
#pragma unroll
    for (int r = 0; r < 4; ++r) {
        float c0, c1, c2, c3;
        unpack2(acc[r][0], c0, c1);
        unpack2(acc[r][1], c2, c3);
        long orow = m0 + ty * 4 + r;
        float4 v;
        v.x = c0 + bi0; v.y = c1 + bi1; v.z = c2 + bi2; v.w = c3 + bi3;
        *(float4*)&out[orow * H4 + n0 + tx * 4] = v;
    }
}

// ---------------------------------------------------------------------------
// Recurrent sweep for one encoder layer: block owns TB batch rows, loops all
// SEQ steps internally. gates = Xg[t] + h @ WhhT ; cell update ; h stays in smem,
// c stays in registers. Writes ys (next layer input) and final h,c.
// ---------------------------------------------------------------------------
__global__ void __launch_bounds__(256) k_lstm_seq(const float* __restrict__ WhhT,
                                                  float* __restrict__ ys,
                                                  float* __restrict__ hfin,
                                                  float* __restrict__ cfin) {
    __shared__ float h_s[H][TB + 2];      // k-major; +2 pad keeps 8B alignment
    __shared__ float gates_s[TB][H4];
    const int tid = threadIdx.x;
    const int b0 = blockIdx.x * TB;
    const int col = tid & 127, half = tid >> 7;

    for (int i = tid; i < H * (TB + 2); i += 256) ((float*)h_s)[i] = 0.f;
    float c_reg[8];
#pragma unroll
    for (int r = 0; r < 8; ++r) c_reg[r] = 0.f;
    __syncthreads();

    const int g0 = tid, g1 = tid + 256;
    for (int t = 0; t < SEQ; ++t) {
        // ---- gate phase: 2 gate columns x 16 batch rows per thread ----
        ull acc[8][2];
        ull z = pack2(0.f, 0.f);
#pragma unroll
        for (int bp = 0; bp < 8; ++bp) { acc[bp][0] = z; acc[bp][1] = z; }

#pragma unroll 2
        for (int k = 0; k < H; ++k) {
            float w0 = WhhT[k * H4 + g0];
            float w1 = WhhT[k * H4 + g1];
            ull ww0 = pack2(w0, w0);
            ull ww1 = pack2(w1, w1);
#pragma unroll
            for (int bp = 0; bp < 8; ++bp) {
                ull h2 = *(const ull*)&h_s[k][bp * 2];
                ffma2(acc[bp][0], ww0, h2);
                ffma2(acc[bp][1], ww1, h2);
            }
        }
        const float* xg = g_Xg + ((long)t * BATCH + b0) * H4;
#pragma unroll
        for (int bp = 0; bp < 8; ++bp) {
            float v0, v1;
            unpack2(acc[bp][0], v0, v1);
            gates_s[2 * bp][g0]     = v0 + xg[(2 * bp) * H4 + g0];
            gates_s[2 * bp + 1][g0] = v1 + xg[(2 * bp + 1) * H4 + g0];
            unpack2(acc[bp][1], v0, v1);
            gates_s[2 * bp][g1]     = v0 + xg[(2 * bp) * H4 + g1];
            gates_s[2 * bp + 1][g1] = v1 + xg[(2 * bp + 1) * H4 + g1];
        }
        __syncthreads();
        // ---- cell phase: thread owns (col, 8 batch rows) ----
#pragma unroll
        for (int r = 0; r < 8; ++r) {
            int b = r * 2 + half;
            float gi = gates_s[b][col];
            float gf = gates_s[b][col + 128];
            float gg = gates_s[b][col + 256];
            float go = gates_s[b][col + 384];
            float cn = sigf(gf) * c_reg[r] + sigf(gi) * tanhf(gg);
            c_reg[r] = cn;
            float hn = sigf(go) * tanhf(cn);
            h_s[col][b] = hn;
            ys[((long)t * BATCH + b0 + b) * H + col] = hn;
        }
        __syncthreads();
    }
#pragma unroll
    for (int r = 0; r < 8; ++r) {
        int b = r * 2 + half;
        hfin[(b0 + b) * H + col] = h_s[col][b];
        cfin[(b0 + b) * H + col] = c_reg[r];
    }
}

// ---------------------------------------------------------------------------
// Fused decoder: single launch. Block owns DTB batch rows; loops t=0..T-1 and
// l=0..3 internally (the whole decoder is batch-independent). h in smem, c in
// registers, fc feedback through smem.
// ---------------------------------------------------------------------------
__global__ void __launch_bounds__(256) k_decoder(const float* __restrict__ x,
                                                 const float* __restrict__ dec_b,
                                                 const float* __restrict__ fc_b,
                                                 float* __restrict__ out) {
    __shared__ float h_s[NL][H][DTB + 2];
    __shared__ float gates_s[DTB][H4];
    __shared__ float din_s[IN_DIM][DTB + 2];
    const int tid = threadIdx.x;
    const int b0 = blockIdx.x * DTB;
    const int col = tid & 127, half = tid >> 7;

    // initial states = encoder finals
    for (int i = tid; i < NL * H * DTB; i += 256) {
        int l = i / (H * DTB);
        int rem = i % (H * DTB);
        int k = rem / DTB, b = rem % DTB;
        h_s[l][k][b] = g_h[(l * BATCH + b0 + b) * H + k];
    }
    float c_reg[NL * 4];
#pragma unroll
    for (int l = 0; l < NL; ++l)
#pragma unroll
        for (int r = 0; r < 4; ++r) {
            int b = r * 2 + half;
            c_reg[l * 4 + r] = g_c[(l * BATCH + b0 + b) * H + col];
        }
    for (int i = tid; i < IN_DIM * DTB; i += 256) {
        int j = i / DTB, b = i % DTB;
        din_s[j][b] = x[((long)(b0 + b) * SEQ + (SEQ - 1)) * IN_DIM + j];
    }
    __syncthreads();

    const int g0 = tid, g1 = tid + 256;
    for (int t = 0; t < TDEC; ++t) {
        for (int l = 0; l < NL; ++l) {
            ull acc[4][2];
            ull z = pack2(0.f, 0.f);
#pragma unroll
            for (int bp = 0; bp < 4; ++bp) { acc[bp][0] = z; acc[bp][1] = z; }

            // recurrent part
            const float* WhhT = g_decWhhT + l * H * H4;
#pragma unroll 2
            for (int k = 0; k < H; ++k) {
                float w0 = WhhT[k * H4 + g0];
                float w1 = WhhT[k * H4 + g1];
                ull ww0 = pack2(w0, w0), ww1 = pack2(w1, w1);
#pragma unroll
                for (int bp = 0; bp < 4; ++bp) {
                    ull h2 = *(const ull*)&h_s[l][k][bp * 2];
                    ffma2(acc[bp][0], ww0, h2);
                    ffma2(acc[bp][1], ww1, h2);
                }
            }
            // input part
            if (l == 0) {
                const float* WT = g_decWih0T;
#pragma unroll 2
                for (int k = 0; k < IN_DIM; ++k) {
                    float w0 = WT[k * H4 + g0];
                    float w1 = WT[k * H4 + g1];
                    ull ww0 = pack2(w0, w0), ww1 = pack2(w1, w1);
#pragma unroll
                    for (int bp = 0; bp < 4; ++bp) {
                        ull x2 = *(const ull*)&din_s[k][bp * 2];
                        ffma2(acc[bp][0], ww0, x2);
                        ffma2(acc[bp][1], ww1, x2);
                    }
                }
            } else {
                const float* WT = g_decWihRT + (l - 1) * H * H4;
#pragma unroll 2
                for (int k = 0; k < H; ++k) {
                    float w0 = WT[k * H4 + g0];
                    float w1 = WT[k * H4 + g1];
                    ull ww0 = pack2(w0, w0), ww1 = pack2(w1, w1);
#pragma unroll
                    for (int bp = 0; bp < 4; ++bp) {
                        ull x2 = *(const ull*)&h_s[l - 1][k][bp * 2];
                        ffma2(acc[bp][0], ww0, x2);
                        ffma2(acc[bp][1], ww1, x2);
                    }
                }
            }
            float bb0 = dec_b[l * H4 + g0];
            float bb1 = dec_b[l * H4 + g1];
#pragma unroll
            for (int bp = 0; bp < 4; ++bp) {
                float v0, v1;
                unpack2(acc[bp][0], v0, v1);
                gates_s[2 * bp][g0]     = v0 + bb0;
                gates_s[2 * bp + 1][g0] = v1 + bb0;
                unpack2(acc[bp][1], v0, v1);
                gates_s[2 * bp][g1]     = v0 + bb1;
                gates_s[2 * bp + 1][g1] = v1 + bb1;
            }
            __syncthreads();
#pragma unroll
            for (int r = 0; r < 4; ++r) {
                int b = r * 2 + half;
                float gi = gates_s[b][col];
                float gf = gates_s[b][col + 128];
                float gg = gates_s[b][col + 256];
                float go = gates_s[b][col + 384];
                float cn = sigf(gf) * c_reg[l * 4 + r] + sigf(gi) * tanhf(gg);
                c_reg[l * 4 + r] = cn;
                h_s[l][col][b] = sigf(go) * tanhf(cn);
            }
            __syncthreads();
        }
        // fc: out = h3 @ fcT + fc_b ; also feeds next step's input
        for (int idx = tid; idx < DTB * IN_DIM; idx += 256) {
            int b = idx / IN_DIM, j = idx % IN_DIM;
            float s = fc_b[j];
#pragma unroll 4
            for (int k = 0; k < H; ++k)
                s += h_s[NL - 1][k][b] * g_fcT[k * IN_DIM + j];
            out[((long)(b0 + b) * TDEC + t) * IN_DIM + j] = s;
            din_s[j][b] = s;
        }
        __syncthreads();
    }
}

// ---------------------------------------------------------------------------
// Host launcher (graph-capturable, allocation-free)
// ---------------------------------------------------------------------------
extern "C" void kernel_launch(void* const* d_in, const int* in_sizes, int n_in,
                              void* d_out, int out_size) {
    const float* x        = (const float*)d_in[0];
    const float* enc_Wih0 = (const float*)d_in[2];
    const float* enc_WihR = (const float*)d_in[3];
    const float* enc_Whh  = (const float*)d_in[4];
    const float* enc_b    = (const float*)d_in[5];
    const float* dec_Wih0 = (const float*)d_in[6];
    const float* dec_WihR = (const float*)d_in[7];
    const float* dec_Whh  = (const float*)d_in[8];
    const float* dec_b    = (const float*)d_in[9];
    const float* fc_W     = (const float*)d_in[10];
    const float* fc_b     = (const float*)d_in[11];
    float* out = (float*)d_out;

    float *encWih0T, *encWihRT, *encWhhT, *decWih0T, *decWihRT, *decWhhT, *fcT;
    float *Xg, *ys, *hSt, *cSt;
    cudaGetSymbolAddress((void**)&encWih0T, g_encWih0T);
    cudaGetSymbolAddress((void**)&encWihRT, g_encWihRT);
    cudaGetSymbolAddress((void**)&encWhhT,  g_encWhhT);
    cudaGetSymbolAddress((void**)&decWih0T, g_decWih0T);
    cudaGetSymbolAddress((void**)&decWihRT, g_decWihRT);
    cudaGetSymbolAddress((void**)&decWhhT,  g_decWhhT);
    cudaGetSymbolAddress((void**)&fcT,      g_fcT);
    cudaGetSymbolAddress((void**)&Xg,       g_Xg);
    cudaGetSymbolAddress((void**)&ys,       g_ys);
    cudaGetSymbolAddress((void**)&hSt,      g_h);
    cudaGetSymbolAddress((void**)&cSt,      g_c);

    auto tr = [](const float* src, float* dst, int R, int C) {
        int n = R * C;
        k_transpose<<<(n + 255) / 256, 256>>>(src, dst, R, C);
    };
    tr(enc_Wih0, encWih0T, H4, IN_DIM);
    for (int r = 0; r < 3; ++r) tr(enc_WihR + r * H4 * H, encWihRT + r * H * H4, H4, H);
    for (int l = 0; l < NL; ++l) tr(enc_Whh + l * H4 * H, encWhhT + l * H * H4, H4, H);
    tr(dec_Wih0, decWih0T, H4, IN_DIM);
    for (int r = 0; r < 3; ++r) tr(dec_WihR + r * H4 * H, decWihRT + r * H * H4, H4, H);
    for (int l = 0; l < NL; ++l) tr(dec_Whh + l * H4 * H, decWhhT + l * H * H4, H4, H);
    tr(fc_W, fcT, IN_DIM, H);

    dim3 ggrid(SEQ * BATCH / 64, H4 / 64);

    // encoder layer 0
    k_ingemm<IN_DIM, true><<<ggrid, 256>>>(x, encWih0T, enc_b, Xg);
    k_lstm_seq<<<BATCH / TB, 256>>>(encWhhT, ys, hSt, cSt);
    // encoder layers 1..3 (ys reused in place: GEMM consumes it fully first)
    for (int l = 1; l < NL; ++l) {
        k_ingemm<H, false><<<ggrid, 256>>>(ys, encWihRT + (l - 1) * H * H4,
                                           enc_b + l * H4, Xg);
        k_lstm_seq<<<BATCH / TB, 256>>>(encWhhT + l * H * H4, ys,
                                        hSt + l * BATCH * H, cSt + l * BATCH * H);
    }
    // fused decoder (single launch)
    k_decoder<<<BATCH / DTB, 256>>>(x, dec_b, fc_b, out);
}

// round 3
// speedup vs baseline: 1.5309x; 1.5309x over previous
#include <cuda_runtime.h>
#include <math.h>

// Problem constants
#define IN_DIM 44
#define H      128
#define H4     512
#define NL     4
#define TDEC   50
#define BATCH  2048
#define SEQ    200

#define TB  16   // batch tile per block (encoder recurrent)
#define DTB 16   // batch tile per block (decoder)

typedef unsigned long long ull;

// ---------------------------------------------------------------------------
// Device scratch (static globals: allocation-free kernel_launch)
// ---------------------------------------------------------------------------
__device__ float g_Xg[(long)SEQ * BATCH * H4];  // input-gate contributions (+bias)
__device__ float g_ys[(long)SEQ * BATCH * H];   // layer output sequence
__device__ float g_h[NL * BATCH * H];           // final encoder h per layer
__device__ float g_c[NL * BATCH * H];           // final encoder c per layer
// transposed weights: WT[k][g] layout ([K][4H])
__device__ float g_encWih0T[IN_DIM * H4];
__device__ float g_encWihRT[3 * H * H4];
__device__ float g_encWhhT[NL * H * H4];
__device__ float g_decWih0T[IN_DIM * H4];
__device__ float g_decWihRT[3 * H * H4];
__device__ float g_decWhhT[NL * H * H4];
__device__ float g_fcT[H * IN_DIM];

// ---------------------------------------------------------------------------
// packed f32x2 helpers (FFMA2 — 2x fp32 FMA per instruction on sm_103a)
// ---------------------------------------------------------------------------
__device__ __forceinline__ ull pack2(float a, float b) {
    ull r; asm("mov.b64 %0, {%1,%2};" : "=l"(r) : "f"(a), "f"(b)); return r;
}
__device__ __forceinline__ void unpack2(ull v, float& a, float& b) {
    asm("mov.b64 {%0,%1}, %2;" : "=f"(a), "=f"(b) : "l"(v));
}
__device__ __forceinline__ void ffma2(ull& d, ull a, ull b) {
    asm("fma.rn.f32x2 %0, %1, %2, %0;" : "+l"(d) : "l"(a), "l"(b));
}

// ---------------------------------------------------------------------------
// Fast activations (MUFU-based, ~1e-7 error; harness has no fast-math flag
// so libm expf/tanhf would expand to huge precise sequences)
// ---------------------------------------------------------------------------
__device__ __forceinline__ float sigf(float x) {
    return __fdividef(1.0f, 1.0f + __expf(-x));
}
__device__ __forceinline__ float tanh_fast(float x) {
    float ax = fabsf(x);
    float e = __expf(-2.0f * ax);
    float t = __fdividef(1.0f - e, 1.0f + e);
    return copysignf(t, x);
}

// ---------------------------------------------------------------------------
// Multi-job transpose: src [R][C] -> dst[c*R + r]; one launch handles many
// weight matrices (keeps launch count low so ncu -s 5 lands on the LSTM kernel)
// ---------------------------------------------------------------------------
struct TJob { const float* s; float* d; int R; int C; };
struct TJobs { TJob j[9]; int n; };

__global__ void k_trans_multi(TJobs jobs) {
    int job = blockIdx.y;
    if (job >= jobs.n) return;
    TJob J = jobs.j[job];
    int tot = J.R * J.C;
    for (int i = blockIdx.x * blockDim.x + threadIdx.x; i < tot;
         i += gridDim.x * blockDim.x) {
        int r = i / J.C, c = i % J.C;
        J.d[c * J.R + r] = J.s[i];
    }
}

// ---------------------------------------------------------------------------
// Input GEMM: out[r][n] = bias[n] + sum_k A(r,k) * WT[k][n]
// ---------------------------------------------------------------------------
template <int KDIM, bool GATHER>
__global__ void __launch_bounds__(256) k_ingemm(const float* __restrict__ A,
                                                const float* __restrict__ WT,
                                                const float* __restrict__ bias,
                                                float* __restrict__ out) {
    __shared__ float As[16][65];
    __shared__ float Bs[16][64];
    const int m0 = blockIdx.x * 64;
    const int n0 = blockIdx.y * 64;
    const int tid = threadIdx.x;
    const int tx = tid & 15, ty = tid >> 4;

    ull acc[4][2];
    ull z = pack2(0.f, 0.f);
#pragma unroll
    for (int r = 0; r < 4; ++r) { acc[r][0] = z; acc[r][1] = z; }

    const int KT = (KDIM + 15) / 16;
    for (int kb = 0; kb < KT; ++kb) {
        const int k0 = kb * 16;
#pragma unroll
        for (int i = 0; i < 4; ++i) {
            int idx = tid + i * 256;
            int ka = idx & 15, ma = idx >> 4;
            float va = 0.f;
            if (k0 + ka < KDIM) {
                long off;
                if (GATHER) {
                    int row = m0 + ma;
                    int t = row >> 11;           // BATCH = 2048
                    int b = row & 2047;
                    off = ((long)b * SEQ + t) * KDIM + (k0 + ka);
                } else {
                    off = (long)(m0 + ma) * KDIM + (k0 + ka);
                }
                va = A[off];
            }
            As[ka][ma] = va;
            int nb = idx & 63, kbb = idx >> 6;
            float vb = (k0 + kbb < KDIM) ? WT[(k0 + kbb) * H4 + n0 + nb] : 0.f;
            Bs[kbb][nb] = vb;
        }
        __syncthreads();
#pragma unroll
        for (int k = 0; k < 16; ++k) {
            ull b01 = *(const ull*)&Bs[k][tx * 4];
            ull b23 = *(const ull*)&Bs[k][tx * 4 + 2];
#pragma unroll
            for (int r = 0; r < 4; ++r) {
                float a = As[k][ty * 4 + r];
                ull aa = pack2(a, a);
                ffma2(acc[r][0], aa, b01);
                ffma2(acc[r][1], aa, b23);
            }
        }
        __syncthreads();
    }
    float bi0 = bias[n0 + tx * 4 + 0];
    float bi1 = bias[n0 + tx * 4 + 1];
    float bi2 = bias[n0 + tx * 4 + 2];
    float bi3 = bias[n0 + tx * 4 + 3];
#pragma unroll
    for (int r = 0; r < 4; ++r) {
        float c0, c1, c2, c3;
        unpack2(acc[r][0], c0, c1);
        unpack2(acc[r][1], c2, c3);
        long orow = m0 + ty * 4 + r;
        float4 v;
        v.x = c0 + bi0; v.y = c1 + bi1; v.z = c2 + bi2; v.w = c3 + bi3;
        *(float4*)&out[orow * H4 + n0 + tx * 4] = v;
    }
}

// ---------------------------------------------------------------------------
// Recurrent sweep for one encoder layer. Thread owns gate cols (2*tid, 2*tid+1)
// across TB=16 batch rows; weights fetched as float2 with deep unroll for MLP.
// ---------------------------------------------------------------------------
__global__ void __launch_bounds__(256) k_lstm_seq(const float* __restrict__ WhhT,
                                                  float* __restrict__ ys,
                                                  float* __restrict__ hfin,
                                                  float* __restrict__ cfin) {
    __shared__ float h_s[H][TB + 2];
    __shared__ float gates_s[TB][H4];
    const int tid = threadIdx.x;
    const int b0 = blockIdx.x * TB;
    const int col = tid & 127, half = tid >> 7;

    for (int i = tid; i < H * (TB + 2); i += 256) ((float*)h_s)[i] = 0.f;
    float c_reg[8];
#pragma unroll
    for (int r = 0; r < 8; ++r) c_reg[r] = 0.f;
    __syncthreads();

    const float* wcol = WhhT + 2 * tid;
    for (int t = 0; t < SEQ; ++t) {
        ull acc[8][2];
        ull z = pack2(0.f, 0.f);
#pragma unroll
        for (int bp = 0; bp < 8; ++bp) { acc[bp][0] = z; acc[bp][1] = z; }

#pragma unroll 8
        for (int k = 0; k < H; ++k) {
            float2 w = *(const float2*)(wcol + (long)k * H4);
            ull wwA = pack2(w.x, w.x);
            ull wwB = pack2(w.y, w.y);
#pragma unroll
            for (int bp = 0; bp < 8; ++bp) {
                ull h2 = *(const ull*)&h_s[k][bp * 2];
                ffma2(acc[bp][0], wwA, h2);
                ffma2(acc[bp][1], wwB, h2);
            }
        }
        const float* xg = g_Xg + ((long)t * BATCH + b0) * H4 + 2 * tid;
#pragma unroll
        for (int bp = 0; bp < 8; ++bp) {
            float a0, a1, bq0, bq1;
            unpack2(acc[bp][0], a0, a1);
            unpack2(acc[bp][1], bq0, bq1);
            float2 x0 = *(const float2*)&xg[(2 * bp) * H4];
            float2 x1 = *(const float2*)&xg[(2 * bp + 1) * H4];
            float2 v0; v0.x = a0 + x0.x; v0.y = bq0 + x0.y;
            float2 v1; v1.x = a1 + x1.x; v1.y = bq1 + x1.y;
            *(float2*)&gates_s[2 * bp][2 * tid]     = v0;
            *(float2*)&gates_s[2 * bp + 1][2 * tid] = v1;
        }
        __syncthreads();
#pragma unroll
        for (int r = 0; r < 8; ++r) {
            int b = r * 2 + half;
            float gi = gates_s[b][col];
            float gf = gates_s[b][col + 128];
            float gg = gates_s[b][col + 256];
            float go = gates_s[b][col + 384];
            float cn = sigf(gf) * c_reg[r] + sigf(gi) * tanh_fast(gg);
            c_reg[r] = cn;
            float hn = sigf(go) * tanh_fast(cn);
            h_s[col][b] = hn;
            ys[((long)t * BATCH + b0 + b) * H + col] = hn;
        }
        __syncthreads();
    }
#pragma unroll
    for (int r = 0; r < 8; ++r) {
        int b = r * 2 + half;
        hfin[(b0 + b) * H + col] = h_s[col][b];
        cfin[(b0 + b) * H + col] = c_reg[r];
    }
}

// ---------------------------------------------------------------------------
// Fused decoder: 128 blocks (DTB=16), dynamic smem (72.8 KB).
// ---------------------------------------------------------------------------
#define DPAD (DTB + 2)
#define HS_F   (NL * H * DPAD)     // 9216 floats
#define GATE_F (DTB * H4)          // 8192 floats
#define DIN_F  (IN_DIM * DPAD)     // 792 floats
#define DEC_SMEM_BYTES ((HS_F + GATE_F + DIN_F) * 4)

__global__ void __launch_bounds__(256) k_decoder(const float* __restrict__ x,
                                                 const float* __restrict__ dec_b,
                                                 const float* __restrict__ fc_b,
                                                 float* __restrict__ out) {
    extern __shared__ float dsm[];
    float* h_s    = dsm;                 // [l][k][b] : ((l*H)+k)*DPAD + b
    float* gates_s = dsm + HS_F;         // [b][g]    : b*H4 + g
    float* din_s  = gates_s + GATE_F;    // [j][b]    : j*DPAD + b

    const int tid = threadIdx.x;
    const int b0 = blockIdx.x * DTB;
    const int col = tid & 127, half = tid >> 7;

    for (int i = tid; i < NL * H * DTB; i += 256) {
        int l = i / (H * DTB);
        int rem = i % (H * DTB);
        int k = rem / DTB, b = rem % DTB;
        h_s[(l * H + k) * DPAD + b] = g_h[(l * BATCH + b0 + b) * H + k];
    }
    float c_reg[NL * 8];
#pragma unroll
    for (int l = 0; l < NL; ++l)
#pragma unroll
        for (int r = 0; r < 8; ++r) {
            int b = r * 2 + half;
            c_reg[l * 8 + r] = g_c[(l * BATCH + b0 + b) * H + col];
        }
    for (int i = tid; i < IN_DIM * DTB; i += 256) {
        int j = i / DTB, b = i % DTB;
        din_s[j * DPAD + b] = x[((long)(b0 + b) * SEQ + (SEQ - 1)) * IN_DIM + j];
    }
    __syncthreads();

    for (int t = 0; t < TDEC; ++t) {
        for (int l = 0; l < NL; ++l) {
            ull acc[8][2];
            ull z = pack2(0.f, 0.f);
#pragma unroll
            for (int bp = 0; bp < 8; ++bp) { acc[bp][0] = z; acc[bp][1] = z; }

            // recurrent part
            const float* wr = g_decWhhT + (long)l * H * H4 + 2 * tid;
#pragma unroll 8
            for (int k = 0; k < H; ++k) {
                float2 w = *(const float2*)(wr + (long)k * H4);
                ull wwA = pack2(w.x, w.x), wwB = pack2(w.y, w.y);
                const float* hrow = h_s + (l * H + k) * DPAD;
#pragma unroll
                for (int bp = 0; bp < 8; ++bp) {
                    ull h2 = *(const ull*)&hrow[bp * 2];
                    ffma2(acc[bp][0], wwA, h2);
                    ffma2(acc[bp][1], wwB, h2);
                }
            }
            // input part
            if (l == 0) {
                const float* wi = g_decWih0T + 2 * tid;
#pragma unroll 4
                for (int k = 0; k < IN_DIM; ++k) {
                    float2 w = *(const float2*)(wi + (long)k * H4);
                    ull wwA = pack2(w.x, w.x), wwB = pack2(w.y, w.y);
                    const float* drow = din_s + k * DPAD;
#pragma unroll
                    for (int bp = 0; bp < 8; ++bp) {
                        ull x2 = *(const ull*)&drow[bp * 2];
                        ffma2(acc[bp][0], wwA, x2);
                        ffma2(acc[bp][1], wwB, x2);
                    }
                }
            } else {
                const float* wi = g_decWihRT + (long)(l - 1) * H * H4 + 2 * tid;
#pragma unroll 8
                for (int k = 0; k < H; ++k) {
                    float2 w = *(const float2*)(wi + (long)k * H4);
                    ull wwA = pack2(w.x, w.x), wwB = pack2(w.y, w.y);
                    const float* hrow = h_s + ((l - 1) * H + k) * DPAD;
#pragma unroll
                    for (int bp = 0; bp < 8; ++bp) {
                        ull x2 = *(const ull*)&hrow[bp * 2];
                        ffma2(acc[bp][0], wwA, x2);
                        ffma2(acc[bp][1], wwB, x2);
                    }
                }
            }
            float2 bb = *(const float2*)&dec_b[(long)l * H4 + 2 * tid];
#pragma unroll
            for (int bp = 0; bp < 8; ++bp) {
                float a0, a1, q0, q1;
                unpack2(acc[bp][0], a0, a1);
                unpack2(acc[bp][1], q0, q1);
                float2 v0; v0.x = a0 + bb.x; v0.y = q0 + bb.y;
                float2 v1; v1.x = a1 + bb.x; v1.y = q1 + bb.y;
                *(float2*)&gates_s[(2 * bp) * H4 + 2 * tid]     = v0;
                *(float2*)&gates_s[(2 * bp + 1) * H4 + 2 * tid] = v1;
            }
            __syncthreads();
#pragma unroll
            for (int r = 0; r < 8; ++r) {
                int b = r * 2 + half;
                float gi = gates_s[b * H4 + col];
                float gf = gates_s[b * H4 + col + 128];
                float gg = gates_s[b * H4 + col + 256];
                float go = gates_s[b * H4 + col + 384];
                float cn = sigf(gf) * c_reg[l * 8 + r] + sigf(gi) * tanh_fast(gg);
                c_reg[l * 8 + r] = cn;
                h_s[(l * H + col) * DPAD + b] = sigf(go) * tanh_fast(cn);
            }
            __syncthreads();
        }
        // fc: out = h3 @ fcT + fc_b ; feeds next step's input
        for (int idx = tid; idx < DTB * IN_DIM; idx += 256) {
            int b = idx / IN_DIM, j = idx % IN_DIM;
            float s = fc_b[j];
            const float* h3 = h_s + (NL - 1) * H * DPAD + b;
#pragma unroll 8
            for (int k = 0; k < H; ++k)
                s += h3[k * DPAD] * g_fcT[k * IN_DIM + j];
            out[((long)(b0 + b) * TDEC + t) * IN_DIM + j] = s;
            din_s[j * DPAD + b] = s;
        }
        __syncthreads();
    }
}

// ---------------------------------------------------------------------------
// Host launcher (graph-capturable, allocation-free)
// ---------------------------------------------------------------------------
extern "C" void kernel_launch(void* const* d_in, const int* in_sizes, int n_in,
                              void* d_out, int out_size) {
    const float* x        = (const float*)d_in[0];
    const float* enc_Wih0 = (const float*)d_in[2];
    const float* enc_WihR = (const float*)d_in[3];
    const float* enc_Whh  = (const float*)d_in[4];
    const float* enc_b    = (const float*)d_in[5];
    const float* dec_Wih0 = (const float*)d_in[6];
    const float* dec_WihR = (const float*)d_in[7];
    const float* dec_Whh  = (const float*)d_in[8];
    const float* dec_b    = (const float*)d_in[9];
    const float* fc_W     = (const float*)d_in[10];
    const float* fc_b     = (const float*)d_in[11];
    float* out = (float*)d_out;

    float *encWih0T, *encWihRT, *encWhhT, *decWih0T, *decWihRT, *decWhhT, *fcT;
    float *Xg, *ys, *hSt, *cSt;
    cudaGetSymbolAddress((void**)&encWih0T, g_encWih0T);
    cudaGetSymbolAddress((void**)&encWihRT, g_encWihRT);
    cudaGetSymbolAddress((void**)&encWhhT,  g_encWhhT);
    cudaGetSymbolAddress((void**)&decWih0T, g_decWih0T);
    cudaGetSymbolAddress((void**)&decWihRT, g_decWihRT);
    cudaGetSymbolAddress((void**)&decWhhT,  g_decWhhT);
    cudaGetSymbolAddress((void**)&fcT,      g_fcT);
    cudaGetSymbolAddress((void**)&Xg,       g_Xg);
    cudaGetSymbolAddress((void**)&ys,       g_ys);
    cudaGetSymbolAddress((void**)&hSt,      g_h);
    cudaGetSymbolAddress((void**)&cSt,      g_c);

    cudaFuncSetAttribute(k_decoder, cudaFuncAttributeMaxDynamicSharedMemorySize,
                         DEC_SMEM_BYTES);

    // --- transposes: 2 launches ---
    {
        TJobs je; je.n = 8;
        je.j[0] = { enc_Wih0, encWih0T, H4, IN_DIM };
        for (int r = 0; r < 3; ++r)
            je.j[1 + r] = { enc_WihR + (long)r * H4 * H, encWihRT + (long)r * H * H4, H4, H };
        for (int l = 0; l < NL; ++l)
            je.j[4 + l] = { enc_Whh + (long)l * H4 * H, encWhhT + (long)l * H * H4, H4, H };
        dim3 g(64, 8);
        k_trans_multi<<<g, 256>>>(je);

        TJobs jd; jd.n = 9;
        jd.j[0] = { dec_Wih0, decWih0T, H4, IN_DIM };
        for (int r = 0; r < 3; ++r)
            jd.j[1 + r] = { dec_WihR + (long)r * H4 * H, decWihRT + (long)r * H * H4, H4, H };
        for (int l = 0; l < NL; ++l)
            jd.j[4 + l] = { dec_Whh + (long)l * H4 * H, decWhhT + (long)l * H * H4, H4, H };
        jd.j[8] = { fc_W, fcT, IN_DIM, H };
        dim3 g2(64, 9);
        k_trans_multi<<<g2, 256>>>(jd);
    }

    dim3 ggrid(SEQ * BATCH / 64, H4 / 64);

    // encoder layer 0
    k_ingemm<IN_DIM, true><<<ggrid, 256>>>(x, encWih0T, enc_b, Xg);
    k_lstm_seq<<<BATCH / TB, 256>>>(encWhhT, ys, hSt, cSt);
    // encoder layers 1..3
    for (int l = 1; l < NL; ++l) {
        k_ingemm<H, false><<<ggrid, 256>>>(ys, encWihRT + (long)(l - 1) * H * H4,
                                           enc_b + (long)l * H4, Xg);
        k_lstm_seq<<<BATCH / TB, 256>>>(encWhhT + (long)l * H * H4, ys,
                                        hSt + (long)l * BATCH * H, cSt + (long)l * BATCH * H);
    }
    // fused decoder (single launch)
    k_decoder<<<BATCH / DTB, 256, DEC_SMEM_BYTES>>>(x, dec_b, fc_b, out);
}